// round 6
// baseline (speedup 1.0000x reference)
#include <cuda_runtime.h>
#include <math.h>

#define N_NODES  100000
#define N_EDGES  1600000
#define DIM      128
#define NCLS     40
#define NB       ((N_NODES + 255) / 256)   // 391 scan blocks

typedef unsigned long long u64;

// Scratch (no allocation allowed)
__device__ float g_x1 [(size_t)N_NODES * DIM];
__device__ int   g_deg[N_NODES];
__device__ int   g_start[N_NODES];
__device__ int   g_cursor[N_NODES];
__device__ int   g_blocksum[NB];
__device__ int   g_col[N_EDGES];

// ---------------------------------------------------------------------------
// f32x2 helpers (sm_103a packed fp32 FMA — 2x scalar FFMA throughput)
// ---------------------------------------------------------------------------
__device__ __forceinline__ u64 bcast2(float v) {
    u64 r; asm("mov.b64 %0, {%1, %2};" : "=l"(r) : "f"(v), "f"(v)); return r;
}
__device__ __forceinline__ void ffma2(u64& d, u64 a, u64 b) {
    asm("fma.rn.f32x2 %0, %1, %2, %0;" : "+l"(d) : "l"(a), "l"(b));
}
__device__ __forceinline__ float2 unpk(u64 v) {
    float lo, hi; asm("mov.b64 {%0, %1}, %2;" : "=f"(lo), "=f"(hi) : "l"(v));
    return make_float2(lo, hi);
}

// ---------------------------------------------------------------------------
// CSR build: degree count -> 2-level exclusive scan -> fill
// ---------------------------------------------------------------------------
__global__ void zero_deg_kernel() {
    int i = blockIdx.x * blockDim.x + threadIdx.x;
    if (i < N_NODES) g_deg[i] = 0;
}

__global__ void count_kernel(const int2* __restrict__ edges) {
    int i = blockIdx.x * blockDim.x + threadIdx.x;
    if (i < N_EDGES) atomicAdd(&g_deg[__ldg(&edges[i]).y], 1);
}

__global__ void block_sum_kernel() {
    __shared__ int sm[256];
    int i = blockIdx.x * 256 + threadIdx.x;
    sm[threadIdx.x] = (i < N_NODES) ? g_deg[i] : 0;
    __syncthreads();
    for (int s = 128; s > 0; s >>= 1) {
        if (threadIdx.x < s) sm[threadIdx.x] += sm[threadIdx.x + s];
        __syncthreads();
    }
    if (threadIdx.x == 0) g_blocksum[blockIdx.x] = sm[0];
}

__global__ void top_scan_kernel() {   // 1 block, 512 threads, NB=391 <= 512
    __shared__ int sm[512];
    int t = threadIdx.x;
    sm[t] = (t < NB) ? g_blocksum[t] : 0;
    __syncthreads();
    for (int off = 1; off < 512; off <<= 1) {
        int v = (t >= off) ? sm[t - off] : 0;
        __syncthreads();
        sm[t] += v;
        __syncthreads();
    }
    if (t < NB) g_blocksum[t] = (t == 0) ? 0 : sm[t - 1];   // exclusive
}

__global__ void final_scan_kernel() {
    __shared__ int sm[256];
    int t = threadIdx.x;
    int i = blockIdx.x * 256 + t;
    int d = (i < N_NODES) ? g_deg[i] : 0;
    sm[t] = d;
    __syncthreads();
    for (int off = 1; off < 256; off <<= 1) {
        int v = (t >= off) ? sm[t - off] : 0;
        __syncthreads();
        sm[t] += v;
        __syncthreads();
    }
    if (i < N_NODES) {
        int excl = sm[t] - d + g_blocksum[blockIdx.x];
        g_start[i]  = excl;
        g_cursor[i] = excl;
    }
}

__global__ void fill_kernel(const int2* __restrict__ edges) {
    int i = blockIdx.x * blockDim.x + threadIdx.x;
    if (i < N_EDGES) {
        int2 e = __ldg(&edges[i]);
        int pos = atomicAdd(&g_cursor[e.y], 1);
        g_col[pos] = e.x;
    }
}

// ---------------------------------------------------------------------------
// Warp-cooperative gather of one node row into a float4 accumulator.
// Uses __ldcg (L2-only) so x traffic does not evict L1-resident weights.
// ---------------------------------------------------------------------------
__device__ __forceinline__ float4 gather_row(const float* __restrict__ x,
                                             int node, int lane) {
    float4 acc0 = __ldcg((const float4*)(x + (size_t)node * DIM) + lane);
    float4 acc1 = make_float4(0.f, 0.f, 0.f, 0.f);
    int start = __ldg(&g_start[node]);
    int deg   = __ldg(&g_deg[node]);
    for (int i0 = 0; i0 < deg; i0 += 32) {
        int rem = deg - i0;
        int c = (lane < rem) ? __ldg(&g_col[start + i0 + lane]) : 0;
        int m = min(32, rem);
        int j = 0;
        for (; j + 1 < m; j += 2) {
            int s0 = __shfl_sync(0xffffffffu, c, j);
            int s1 = __shfl_sync(0xffffffffu, c, j + 1);
            float4 v0 = __ldcg((const float4*)(x + (size_t)s0 * DIM) + lane);
            float4 v1 = __ldcg((const float4*)(x + (size_t)s1 * DIM) + lane);
            acc0.x += v0.x; acc0.y += v0.y; acc0.z += v0.z; acc0.w += v0.w;
            acc1.x += v1.x; acc1.y += v1.y; acc1.z += v1.z; acc1.w += v1.w;
        }
        if (j < m) {
            int s0 = __shfl_sync(0xffffffffu, c, j);
            float4 v0 = __ldcg((const float4*)(x + (size_t)s0 * DIM) + lane);
            acc0.x += v0.x; acc0.y += v0.y; acc0.z += v0.z; acc0.w += v0.w;
        }
    }
    acc0.x += acc1.x; acc0.y += acc1.y; acc0.z += acc1.z; acc0.w += acc1.w;
    return acc0;
}

// ---------------------------------------------------------------------------
// Fused layer 1: gather (+self) -> relu(.*Wa+ba) -> relu(.*Wb+bb) -> x1
// 256 threads, 64-row tile. Weights via __ldg (L1-resident, 128 KB total).
// Smem = X tile only (33.8 KB) -> multiple blocks/SM -> gather/GEMM overlap.
// ---------------------------------------------------------------------------
__global__ void __launch_bounds__(256)
fused_l1_kernel(const float* __restrict__ X,
                const float* __restrict__ Wa, const float* __restrict__ ba,
                const float* __restrict__ Wb, const float* __restrict__ bb,
                float* __restrict__ Y) {
    __shared__ float Xs[64 * 132];

    const int tid  = threadIdx.x;
    const int warp = tid >> 5;
    const int lane = tid & 31;
    const int cg   = tid & 15;      // col group: cols [cg*8, cg*8+8)
    const int rg   = tid >> 4;      // row group: rows [rg*4, rg*4+4)
    const int base = blockIdx.x * 64;

    // Gather phase: 8 warps x 8 rows each, accumulate in regs, store to smem.
    for (int r = warp; r < 64; r += 8) {
        int node = base + r;
        float4 acc = (node < N_NODES) ? gather_row(X, node, lane)
                                      : make_float4(0.f, 0.f, 0.f, 0.f);
        *(float4*)(Xs + r * 132 + lane * 4) = acc;
    }
    __syncthreads();

    u64 acc[4][4];   // 4 rows x 4 col-pairs (8 cols)

    // ---- stage 1: H = relu(X*Wa + ba) ----
    {
        ulonglong2 b01 = __ldg((const ulonglong2*)(ba + cg * 8));
        ulonglong2 b23 = __ldg((const ulonglong2*)(ba + cg * 8 + 4));
        #pragma unroll
        for (int i = 0; i < 4; i++) {
            acc[i][0] = b01.x; acc[i][1] = b01.y;
            acc[i][2] = b23.x; acc[i][3] = b23.y;
        }
    }
    #pragma unroll 4
    for (int k = 0; k < 128; k++) {
        ulonglong2 w01 = __ldg((const ulonglong2*)(Wa + k * 128 + cg * 8));
        ulonglong2 w23 = __ldg((const ulonglong2*)(Wa + k * 128 + cg * 8 + 4));
        #pragma unroll
        for (int i = 0; i < 4; i++) {
            u64 xp = bcast2(Xs[(rg * 4 + i) * 132 + k]);
            ffma2(acc[i][0], xp, w01.x);
            ffma2(acc[i][1], xp, w01.y);
            ffma2(acc[i][2], xp, w23.x);
            ffma2(acc[i][3], xp, w23.y);
        }
    }
    __syncthreads();
    #pragma unroll
    for (int i = 0; i < 4; i++) {
        float2 p0 = unpk(acc[i][0]), p1 = unpk(acc[i][1]);
        float2 p2 = unpk(acc[i][2]), p3 = unpk(acc[i][3]);
        float4 a0 = make_float4(fmaxf(p0.x,0.f), fmaxf(p0.y,0.f), fmaxf(p1.x,0.f), fmaxf(p1.y,0.f));
        float4 a1 = make_float4(fmaxf(p2.x,0.f), fmaxf(p2.y,0.f), fmaxf(p3.x,0.f), fmaxf(p3.y,0.f));
        *(float4*)(Xs + (rg * 4 + i) * 132 + cg * 8)     = a0;
        *(float4*)(Xs + (rg * 4 + i) * 132 + cg * 8 + 4) = a1;
    }
    __syncthreads();

    // ---- stage 2: Y = relu(H*Wb + bb) ----
    {
        ulonglong2 b01 = __ldg((const ulonglong2*)(bb + cg * 8));
        ulonglong2 b23 = __ldg((const ulonglong2*)(bb + cg * 8 + 4));
        #pragma unroll
        for (int i = 0; i < 4; i++) {
            acc[i][0] = b01.x; acc[i][1] = b01.y;
            acc[i][2] = b23.x; acc[i][3] = b23.y;
        }
    }
    #pragma unroll 4
    for (int k = 0; k < 128; k++) {
        ulonglong2 w01 = __ldg((const ulonglong2*)(Wb + k * 128 + cg * 8));
        ulonglong2 w23 = __ldg((const ulonglong2*)(Wb + k * 128 + cg * 8 + 4));
        #pragma unroll
        for (int i = 0; i < 4; i++) {
            u64 xp = bcast2(Xs[(rg * 4 + i) * 132 + k]);
            ffma2(acc[i][0], xp, w01.x);
            ffma2(acc[i][1], xp, w01.y);
            ffma2(acc[i][2], xp, w23.x);
            ffma2(acc[i][3], xp, w23.y);
        }
    }
    #pragma unroll
    for (int i = 0; i < 4; i++) {
        int row = base + rg * 4 + i;
        if (row < N_NODES) {
            float2 p0 = unpk(acc[i][0]), p1 = unpk(acc[i][1]);
            float2 p2 = unpk(acc[i][2]), p3 = unpk(acc[i][3]);
            float4 a0 = make_float4(fmaxf(p0.x,0.f), fmaxf(p0.y,0.f), fmaxf(p1.x,0.f), fmaxf(p1.y,0.f));
            float4 a1 = make_float4(fmaxf(p2.x,0.f), fmaxf(p2.y,0.f), fmaxf(p3.x,0.f), fmaxf(p3.y,0.f));
            *(float4*)(Y + (size_t)row * DIM + cg * 8)     = a0;
            *(float4*)(Y + (size_t)row * DIM + cg * 8 + 4) = a1;
        }
    }
}

// ---------------------------------------------------------------------------
// Fused layer 2: gather (+self) -> relu(.*W2a+b2a) -> .*W2b+b2b -> softmax
// 128 threads, 128-row tile; gather = 4 warps x 32 rows; compute = row/thread.
// Weights via __ldg (uniform-address broadcasts, ~27 KB, L1-resident).
// ---------------------------------------------------------------------------
#define L2_SMEM_BYTES (128 * 132 * 4)

__global__ void __launch_bounds__(128)
fused_l2_kernel(const float* __restrict__ X,
                const float* __restrict__ Wa, const float* __restrict__ ba,
                const float* __restrict__ Wb, const float* __restrict__ bb,
                float* __restrict__ out) {
    extern __shared__ float Xs[];    // [128][132]

    const int tid  = threadIdx.x;
    const int warp = tid >> 5;
    const int lane = tid & 31;
    const int base = blockIdx.x * 128;

    // Gather phase: 4 warps x 32 rows each.
    for (int r = warp; r < 128; r += 4) {
        int node = base + r;
        if (node < N_NODES) {
            float4 acc = gather_row(X, node, lane);
            *(float4*)(Xs + r * 132 + lane * 4) = acc;
        }
    }
    __syncthreads();

    const int row = base + tid;
    if (row >= N_NODES) return;

    u64 z2[20];
    #pragma unroll
    for (int c = 0; c < 20; c++) z2[c] = __ldg((const u64*)ba + c);

    #pragma unroll 2
    for (int k = 0; k < 128; k++) {
        u64 xp = bcast2(Xs[tid * 132 + k]);
        const ulonglong2* wr = (const ulonglong2*)(Wa + k * 40);
        #pragma unroll
        for (int c2 = 0; c2 < 10; c2++) {
            ulonglong2 w = __ldg(wr + c2);
            ffma2(z2[c2 * 2],     xp, w.x);
            ffma2(z2[c2 * 2 + 1], xp, w.y);
        }
    }
    float z[NCLS];
    #pragma unroll
    for (int c = 0; c < 20; c++) {
        float2 p = unpk(z2[c]);
        z[c * 2]     = fmaxf(p.x, 0.f);
        z[c * 2 + 1] = fmaxf(p.y, 0.f);
    }

    u64 lg2[20];
    #pragma unroll
    for (int c = 0; c < 20; c++) lg2[c] = __ldg((const u64*)bb + c);
    #pragma unroll 4
    for (int j = 0; j < NCLS; j++) {
        u64 zp = bcast2(z[j]);
        const ulonglong2* wr = (const ulonglong2*)(Wb + j * 40);
        #pragma unroll
        for (int c2 = 0; c2 < 10; c2++) {
            ulonglong2 w = __ldg(wr + c2);
            ffma2(lg2[c2 * 2],     zp, w.x);
            ffma2(lg2[c2 * 2 + 1], zp, w.y);
        }
    }
    float lg[NCLS];
    #pragma unroll
    for (int c = 0; c < 20; c++) {
        float2 p = unpk(lg2[c]);
        lg[c * 2] = p.x; lg[c * 2 + 1] = p.y;
    }

    float m = lg[0];
    #pragma unroll
    for (int c = 1; c < NCLS; c++) m = fmaxf(m, lg[c]);
    float s = 0.f;
    #pragma unroll
    for (int c = 0; c < NCLS; c++) { lg[c] = expf(lg[c] - m); s += lg[c]; }
    float inv = 1.f / s;

    #pragma unroll
    for (int c4 = 0; c4 < 10; c4++) {
        float4 v = make_float4(lg[c4*4+0]*inv, lg[c4*4+1]*inv,
                               lg[c4*4+2]*inv, lg[c4*4+3]*inv);
        *(float4*)(out + (size_t)row * NCLS + c4 * 4) = v;
    }
}

// ---------------------------------------------------------------------------
extern "C" void kernel_launch(void* const* d_in, const int* in_sizes, int n_in,
                              void* d_out, int out_size) {
    const float* x   = (const float*)d_in[0];
    const int*   ei  = (const int*)  d_in[1];
    const float* W1a = (const float*)d_in[2];
    const float* b1a = (const float*)d_in[3];
    const float* W1b = (const float*)d_in[4];
    const float* b1b = (const float*)d_in[5];
    const float* W2a = (const float*)d_in[6];
    const float* b2a = (const float*)d_in[7];
    const float* W2b = (const float*)d_in[8];
    const float* b2b = (const float*)d_in[9];
    float* out = (float*)d_out;

    float* x1 = nullptr;
    cudaGetSymbolAddress((void**)&x1, g_x1);

    cudaFuncSetAttribute(fused_l2_kernel, cudaFuncAttributeMaxDynamicSharedMemorySize,
                         L2_SMEM_BYTES);

    const int edge_blocks = (N_EDGES + 255) / 256;       // 6250
    const int node_blocks = NB;                          // 391
    const int l1_blocks   = (N_NODES + 63) / 64;         // 1563
    const int l2_blocks   = (N_NODES + 127) / 128;       // 782

    // CSR build (once; serves both layers)
    zero_deg_kernel  <<<node_blocks, 256>>>();
    count_kernel     <<<edge_blocks, 256>>>((const int2*)ei);
    block_sum_kernel <<<node_blocks, 256>>>();
    top_scan_kernel  <<<1, 512>>>();
    final_scan_kernel<<<node_blocks, 256>>>();
    fill_kernel      <<<edge_blocks, 256>>>((const int2*)ei);

    // Layer 1 (fused gather + MLP)
    fused_l1_kernel<<<l1_blocks, 256>>>(x, W1a, b1a, W1b, b1b, x1);

    // Layer 2 (fused gather + MLP + softmax)
    fused_l2_kernel<<<l2_blocks, 128, L2_SMEM_BYTES>>>(x1, W2a, b2a, W2b, b2b, out);
}